// round 15
// baseline (speedup 1.0000x reference)
#include <cuda_runtime.h>
#include <cuda_bf16.h>
#include <math.h>
#include <stdint.h>

#define BB 8
#define SS 1024
#define HH 1024
#define VV 512
#define LL 6

// ---------------- scratch (device globals; no allocation allowed) -------------
__device__ float g_x[BB * SS * HH];
__device__ float g_q[BB * SS * HH];
__device__ float g_k[BB * SS * HH];   // k; reused as attn^T after logits
__device__ float g_v[BB * SS * HH];
__device__ float g_vt[BB * SS * HH];  // v^T
__device__ float g_c[BB * SS * HH];
__device__ float g_wqt[LL * HH * HH];
__device__ float g_wkt[LL * HH * HH];
__device__ float g_wvt[LL * HH * HH];
__device__ float g_wmt[LL * HH * HH];
__device__ float g_wot[HH * VV];

// ---------------- helpers ------------------------------------------------------
__device__ __forceinline__ uint32_t to_tf32(float x) {
    uint32_t r;
    asm("cvt.rna.tf32.f32 %0, %1;" : "=r"(r) : "f"(x));
    return r;
}
__device__ __forceinline__ void mma_tf32(float* c, const uint32_t* a,
                                         uint32_t b0, uint32_t b1) {
    asm volatile(
        "mma.sync.aligned.m16n8k8.row.col.f32.tf32.tf32.f32 "
        "{%0,%1,%2,%3}, {%4,%5,%6,%7}, {%8,%9}, {%0,%1,%2,%3};"
        : "+f"(c[0]), "+f"(c[1]), "+f"(c[2]), "+f"(c[3])
        : "r"(a[0]), "r"(a[1]), "r"(a[2]), "r"(a[3]), "r"(b0), "r"(b1));
}

// ---------------- small kernels -------------------------------------------------
__global__ void embed_kernel(float* __restrict__ x, const float* __restrict__ emb,
                             const int* __restrict__ ids) {
    int t = blockIdx.x * blockDim.x + threadIdx.x;
    int row = t >> 8;
    int c4  = t & 255;
    const float4* src = (const float4*)(emb + (size_t)ids[row] * HH);
    ((float4*)(x + (size_t)row * HH))[c4] = src[c4];
}

// out[c][r] = in[r][c], per batch z (R rows, C cols)
__global__ void transpose_kernel(const float* __restrict__ in, float* __restrict__ out,
                                 int R, int C) {
    __shared__ float t[32][33];
    const float* ip = in + (size_t)blockIdx.z * R * C;
    float* op = out + (size_t)blockIdx.z * R * C;
    int c0 = blockIdx.x * 32, r0 = blockIdx.y * 32;
    int x = threadIdx.x, y = threadIdx.y;
#pragma unroll
    for (int j = 0; j < 32; j += 8)
        t[y + j][x] = ip[(size_t)(r0 + y + j) * C + c0 + x];
    __syncthreads();
#pragma unroll
    for (int j = 0; j < 32; j += 8)
        op[(size_t)(c0 + y + j) * R + r0 + x] = t[x][y + j];
}

// ---------------- single-product TF32 tensor-core GEMM ---------------------------
// C[M,N] = alpha * A @ B^T (+bias[n]); A:[M,K] lda, B:[N,K] ldb (both K-contig).
// CTA tile 128(M) x 256(N), K-chunk 32, 16 warps of 32x64, tf32 mma m16n8k8.
// EPI=1: C = res1 + res2 + relu(acc + bias)
// mode: 0 none, 1 causal K clamp (Kend=m0+128), 2 skip tile if m0 > n0+255
static constexpr int RP = 36;                         // padded row, floats
static constexpr int SMEM_A_FLOATS = 128 * RP;        // 4608
static constexpr int SMEM_B_FLOATS = 256 * RP;        // 9216
static constexpr int BUF_FLOATS    = SMEM_A_FLOATS + SMEM_B_FLOATS;   // 13824
static constexpr int GEMM_SMEM     = 2 * BUF_FLOATS * 4;              // 110592 B

template <int EPI>
__global__ __launch_bounds__(512, 1) void mma_gemm(
    const float* __restrict__ A, const float* __restrict__ B, float* __restrict__ C,
    int K, int lda, int ldb, int ldc, float alpha,
    const float* __restrict__ bias,
    const float* __restrict__ res1, const float* __restrict__ res2,
    size_t bsA, size_t bsB, size_t bsC, int mode)
{
    extern __shared__ float sm[];
    const int m0 = blockIdx.y * 128;
    const int n0 = blockIdx.x * 256;
    if (mode == 2 && m0 > n0 + 255) return;
    const int bz = blockIdx.z;
    A += (size_t)bz * bsA;
    B += (size_t)bz * bsB;
    C += (size_t)bz * bsC;
    const int Kend = (mode == 1) ? ((m0 + 128 < K) ? m0 + 128 : K) : K;
    const int nch = Kend >> 5;

    const int tid  = threadIdx.x;
    const int lane = tid & 31;
    const int wid  = tid >> 5;     // 0..15
    const int wm   = wid & 3;      // m quarter: rows wm*32
    const int wn   = wid >> 2;     // n quarter: cols wn*64
    const int g    = lane >> 2;    // 0..7
    const int tig  = lane & 3;     // 0..3

    float acc[2][8][4];
#pragma unroll
    for (int i = 0; i < 2; i++)
#pragma unroll
        for (int j = 0; j < 8; j++)
#pragma unroll
            for (int x = 0; x < 4; x++) acc[i][j][x] = 0.f;

    float4 rA[2], rB[4];

    auto loadA = [&](int kc) {
        const int k0 = kc * 32;
#pragma unroll
        for (int i = 0; i < 2; i++) {
            int idx = tid + 512 * i;          // [0,1024): 128 rows x 8 float4
            int r = idx >> 3, c4 = idx & 7;
            rA[i] = *(const float4*)(A + (size_t)(m0 + r) * lda + k0 + c4 * 4);
        }
    };
    auto loadB = [&](int kc) {
        const int k0 = kc * 32;
#pragma unroll
        for (int i = 0; i < 4; i++) {
            int idx = tid + 512 * i;          // [0,2048): 256 rows x 8 float4
            int r = idx >> 3, c4 = idx & 7;
            rB[i] = *(const float4*)(B + (size_t)(n0 + r) * ldb + k0 + c4 * 4);
        }
    };
    auto storeAB = [&](int bufsel) {
        float* bA = sm + bufsel * BUF_FLOATS;
        float* bB = bA + SMEM_A_FLOATS;
#pragma unroll
        for (int i = 0; i < 2; i++) {
            int idx = tid + 512 * i;
            int r = idx >> 3, c4 = idx & 7;
            uint4 t;
            t.x = to_tf32(rA[i].x); t.y = to_tf32(rA[i].y);
            t.z = to_tf32(rA[i].z); t.w = to_tf32(rA[i].w);
            *(uint4*)(bA + r * RP + c4 * 4) = t;
        }
#pragma unroll
        for (int i = 0; i < 4; i++) {
            int idx = tid + 512 * i;
            int r = idx >> 3, c4 = idx & 7;
            uint4 t;
            t.x = to_tf32(rB[i].x); t.y = to_tf32(rB[i].y);
            t.z = to_tf32(rB[i].z); t.w = to_tf32(rB[i].w);
            *(uint4*)(bB + r * RP + c4 * 4) = t;
        }
    };

    loadA(0); loadB(0); storeAB(0);
    __syncthreads();

    for (int c = 0; c < nch; c++) {
        const float* sA = sm + (c & 1) * BUF_FLOATS;
        const float* sB = sA + SMEM_A_FLOATS;
        const bool pf = (c + 1 < nch);
        if (pf) { loadA(c + 1); loadB(c + 1); }

#pragma unroll
        for (int ks = 0; ks < 4; ks++) {
            const int kb = ks * 8;
            uint32_t af[2][4];
#pragma unroll
            for (int mf = 0; mf < 2; mf++) {
                const float* ap = sA + (wm * 32 + mf * 16 + g) * RP + kb + tig;
                af[mf][0] = __float_as_uint(ap[0]);
                af[mf][1] = __float_as_uint(ap[8 * RP]);
                af[mf][2] = __float_as_uint(ap[4]);
                af[mf][3] = __float_as_uint(ap[8 * RP + 4]);
            }
#pragma unroll
            for (int nf = 0; nf < 8; nf++) {
                const float* bp = sB + (wn * 64 + nf * 8 + g) * RP + kb + tig;
                uint32_t b0 = __float_as_uint(bp[0]);
                uint32_t b1 = __float_as_uint(bp[4]);
#pragma unroll
                for (int mf = 0; mf < 2; mf++)
                    mma_tf32(acc[mf][nf], af[mf], b0, b1);
            }
        }

        if (pf) storeAB((c + 1) & 1);
        __syncthreads();
    }

    // ---- epilogue ----
#pragma unroll
    for (int mf = 0; mf < 2; mf++) {
        const int r0 = m0 + wm * 32 + mf * 16 + g;
#pragma unroll
        for (int nf = 0; nf < 8; nf++) {
            const int col = n0 + wn * 64 + nf * 8 + tig * 2;
            float2 v0, v1;
            v0.x = acc[mf][nf][0] * alpha; v0.y = acc[mf][nf][1] * alpha;
            v1.x = acc[mf][nf][2] * alpha; v1.y = acc[mf][nf][3] * alpha;
            if (bias) {
                float2 bb = *(const float2*)(bias + col);
                v0.x += bb.x; v0.y += bb.y; v1.x += bb.x; v1.y += bb.y;
            }
            size_t i0 = (size_t)r0 * ldc + col;
            size_t i1 = i0 + (size_t)8 * ldc;
            if (EPI == 1) {
                float2 p0 = *(const float2*)(res1 + i0), q0 = *(const float2*)(res2 + i0);
                float2 p1 = *(const float2*)(res1 + i1), q1 = *(const float2*)(res2 + i1);
                v0.x = p0.x + q0.x + fmaxf(v0.x, 0.f);
                v0.y = p0.y + q0.y + fmaxf(v0.y, 0.f);
                v1.x = p1.x + q1.x + fmaxf(v1.x, 0.f);
                v1.y = p1.y + q1.y + fmaxf(v1.y, 0.f);
            }
            *(float2*)(C + i0) = v0;
            *(float2*)(C + i1) = v1;
        }
    }
}

// ---------------- causal softmax over key axis + transposed copy ----------------
// attn[b,k,q] in d_out (softmax over k, zeros for k>q); also writes attnT[b,q,k].
// grid: BB*32 blocks (32 q per block), 256 threads = 8 k-slices x 32 q.
__global__ void softmax_kernel(float* __restrict__ attn, float* __restrict__ attnT) {
    __shared__ float rm[8][32], rs[8][32], fM[32], fI[32];
    __shared__ float tile[32][33];
    const int b = blockIdx.x >> 5, qg = blockIdx.x & 31;
    float* base  = attn  + (size_t)b * SS * SS + qg * 32;
    float* baseT = attnT + (size_t)b * SS * SS + (size_t)(qg * 32) * SS;
    const int t  = threadIdx.x;
    const int qi = t & 31;
    const int ks = t >> 5;
    const int q  = qg * 32 + qi;

    float m = -3.4e38f, s = 0.f;
    for (int k = ks; k <= q; k += 8) {
        float x = base[(size_t)k * SS + qi];
        if (x > m) { s = s * __expf(m - x) + 1.f; m = x; }
        else         s += __expf(x - m);
    }
    rm[ks][qi] = m; rs[ks][qi] = s;
    __syncthreads();
    if (t < 32) {
        float M = rm[0][qi];
#pragma unroll
        for (int i = 1; i < 8; i++) M = fmaxf(M, rm[i][qi]);
        float S = 0.f;
#pragma unroll
        for (int i = 0; i < 8; i++) S += rs[i][qi] * __expf(rm[i][qi] - M);
        fM[qi] = M; fI[qi] = 1.f / S;
    }
    __syncthreads();
    const float M = fM[qi], inv = fI[qi];

    for (int kb = 0; kb < 32; kb++) {
#pragma unroll
        for (int j = 0; j < 4; j++) {
            int k = kb * 32 + ks + 8 * j;
            float v = 0.f;
            if (k <= q) v = __expf(base[(size_t)k * SS + qi] - M) * inv;
            base[(size_t)k * SS + qi] = v;
            tile[ks + 8 * j][qi] = v;
        }
        __syncthreads();
        {
            int r = t >> 3, cq = (t & 7) * 4;
            float4 o;
            o.x = tile[cq + 0][r];
            o.y = tile[cq + 1][r];
            o.z = tile[cq + 2][r];
            o.w = tile[cq + 3][r];
            *(float4*)(baseT + (size_t)r * SS + kb * 32 + cq) = o;
        }
        __syncthreads();
    }
}

// ---------------- launch --------------------------------------------------------
extern "C" void kernel_launch(void* const* d_in, const int* in_sizes, int n_in,
                              void* d_out, int out_size) {
    (void)in_sizes; (void)n_in; (void)out_size;

    const int*   inputs    = (const int*)  d_in[0];
    const float* embedding = (const float*)d_in[1];
    const float* Wq = (const float*)d_in[2];
    const float* bq = (const float*)d_in[3];
    const float* Wk = (const float*)d_in[4];
    const float* bk = (const float*)d_in[5];
    const float* Wv = (const float*)d_in[6];
    const float* bv = (const float*)d_in[7];
    const float* Wm = (const float*)d_in[8];
    const float* bm = (const float*)d_in[9];
    const float* Wout = (const float*)d_in[10];
    const float* bout = (const float*)d_in[11];

    float* out   = (float*)d_out;                  // [B,S,V]
    float* attns = out + (size_t)BB * SS * VV;     // [L,B,S,S]

    float *xp, *qp, *kp, *vp, *vtp, *cp, *wqt, *wkt, *wvt, *wmt, *wot;
    cudaGetSymbolAddress((void**)&xp, g_x);
    cudaGetSymbolAddress((void**)&qp, g_q);
    cudaGetSymbolAddress((void**)&kp, g_k);
    cudaGetSymbolAddress((void**)&vp, g_v);
    cudaGetSymbolAddress((void**)&vtp, g_vt);
    cudaGetSymbolAddress((void**)&cp, g_c);
    cudaGetSymbolAddress((void**)&wqt, g_wqt);
    cudaGetSymbolAddress((void**)&wkt, g_wkt);
    cudaGetSymbolAddress((void**)&wvt, g_wvt);
    cudaGetSymbolAddress((void**)&wmt, g_wmt);
    cudaGetSymbolAddress((void**)&wot, g_wot);

    cudaFuncSetAttribute(mma_gemm<0>, cudaFuncAttributeMaxDynamicSharedMemorySize, GEMM_SMEM);
    cudaFuncSetAttribute(mma_gemm<1>, cudaFuncAttributeMaxDynamicSharedMemorySize, GEMM_SMEM);

    // side streams + events for graph-parallel branches (created once; reused)
    static cudaStream_t s1 = nullptr, s2 = nullptr;
    static cudaEvent_t ev_fork = nullptr, ev_wt = nullptr, ev_x = nullptr,
                       ev_v = nullptr, ev_vt = nullptr, ev_k = nullptr;
    if (!s1) {
        cudaStreamCreateWithFlags(&s1, cudaStreamNonBlocking);
        cudaStreamCreateWithFlags(&s2, cudaStreamNonBlocking);
        cudaEventCreateWithFlags(&ev_fork, cudaEventDisableTiming);
        cudaEventCreateWithFlags(&ev_wt,   cudaEventDisableTiming);
        cudaEventCreateWithFlags(&ev_x,    cudaEventDisableTiming);
        cudaEventCreateWithFlags(&ev_v,    cudaEventDisableTiming);
        cudaEventCreateWithFlags(&ev_vt,   cudaEventDisableTiming);
        cudaEventCreateWithFlags(&ev_k,    cudaEventDisableTiming);
    }

    const float scale = 0.03125f;  // 1/sqrt(1024)

    // fork: weight transposes on s1, embed on main
    cudaEventRecord(ev_fork, 0);
    cudaStreamWaitEvent(s1, ev_fork, 0);
    {
        dim3 blk(32, 8);
        dim3 gHH(HH / 32, HH / 32, LL);
        transpose_kernel<<<gHH, blk, 0, s1>>>(Wq, wqt, HH, HH);
        transpose_kernel<<<gHH, blk, 0, s1>>>(Wk, wkt, HH, HH);
        transpose_kernel<<<gHH, blk, 0, s1>>>(Wv, wvt, HH, HH);
        transpose_kernel<<<gHH, blk, 0, s1>>>(Wm, wmt, HH, HH);
        dim3 gO(VV / 32, HH / 32, 1);
        transpose_kernel<<<gO, blk, 0, s1>>>(Wout, wot, HH, VV);
        cudaEventRecord(ev_wt, s1);
    }
    embed_kernel<<<BB * SS * HH / 4 / 256, 256>>>(xp, embedding, inputs);
    cudaStreamWaitEvent(0, ev_wt, 0);

    for (int l = 0; l < LL; l++) {
        const float* wqt_l = wqt + (size_t)l * HH * HH;
        const float* wkt_l = wkt + (size_t)l * HH * HH;
        const float* wvt_l = wvt + (size_t)l * HH * HH;
        const float* wmt_l = wmt + (size_t)l * HH * HH;
        const float* bq_l = bq + (size_t)l * HH;
        const float* bk_l = bk + (size_t)l * HH;
        const float* bv_l = bv + (size_t)l * HH;
        const float* bm_l = bm + (size_t)l * HH;
        float* attn_l = attns + (size_t)l * BB * SS * SS;

        // x ready on main; fork k-projection to s2
        cudaEventRecord(ev_x, 0);
        cudaStreamWaitEvent(s2, ev_x, 0);

        dim3 gProj(HH / 256, BB * SS / 128, 1);   // (4, 64)
        // v first (main) so its transpose overlaps q/logits/softmax on s1
        mma_gemm<0><<<gProj, 512, GEMM_SMEM>>>(xp, wvt_l, vp, HH, HH, HH, HH, 1.f,
                                               bv_l, nullptr, nullptr, 0, 0, 0, 0);
        cudaEventRecord(ev_v, 0);
        cudaStreamWaitEvent(s1, ev_v, 0);
        {
            dim3 blk(32, 8);
            dim3 gV(HH / 32, SS / 32, BB);
            transpose_kernel<<<gV, blk, 0, s1>>>(vp, vtp, SS, HH);  // vt[b][h][s]
            cudaEventRecord(ev_vt, s1);
        }

        // k on s2 (overlaps q's tail), q on main
        mma_gemm<0><<<gProj, 512, GEMM_SMEM, s2>>>(xp, wkt_l, kp, HH, HH, HH, HH, 1.f,
                                                   bk_l, nullptr, nullptr, 0, 0, 0, 0);
        cudaEventRecord(ev_k, s2);
        mma_gemm<0><<<gProj, 512, GEMM_SMEM>>>(xp, wqt_l, qp, HH, HH, HH, HH, 1.f,
                                               bq_l, nullptr, nullptr, 0, 0, 0, 0);
        cudaStreamWaitEvent(0, ev_k, 0);

        // logits[b,k,q] = scale * K[b] @ Q[b]^T ; skip fully-masked tiles
        dim3 gAtt(SS / 256, SS / 128, BB);        // (4, 8, 8)
        mma_gemm<0><<<gAtt, 512, GEMM_SMEM>>>(kp, qp, attn_l, HH, HH, HH, SS, scale,
                                              nullptr, nullptr, nullptr,
                                              (size_t)SS * HH, (size_t)SS * HH,
                                              (size_t)SS * SS, 2);

        // softmax over key axis; also produce attnT into g_k (k no longer needed)
        softmax_kernel<<<BB * 32, 256>>>(attn_l, kp);

        // ctx[b,q,h] = attnT[b] @ vt[b]^T  (A=[q][k], B=[h][k]), causal K clamp
        cudaStreamWaitEvent(0, ev_vt, 0);
        dim3 gCtx(HH / 256, SS / 128, BB);        // (4, 8, 8)
        mma_gemm<0><<<gCtx, 512, GEMM_SMEM>>>(kp, vtp, cp, SS, SS, SS, HH, 1.f,
                                              nullptr, nullptr, nullptr,
                                              (size_t)SS * SS, (size_t)SS * HH,
                                              (size_t)SS * HH, 1);

        // x = x + ctx + relu(ctx@Wm + bm)
        mma_gemm<1><<<gProj, 512, GEMM_SMEM>>>(cp, wmt_l, xp, HH, HH, HH, HH, 1.f,
                                               bm_l, xp, cp, 0, 0, 0, 0);
    }

    // out = x @ Wout + bout
    dim3 gOut(VV / 256, BB * SS / 128, 1);        // (2, 64)
    mma_gemm<0><<<gOut, 512, GEMM_SMEM>>>(xp, wot, out, HH, HH, HH, VV, 1.f,
                                          bout, nullptr, nullptr, 0, 0, 0, 0);
}

// round 17
// speedup vs baseline: 1.1542x; 1.1542x over previous
#include <cuda_runtime.h>
#include <cuda_bf16.h>
#include <math.h>
#include <stdint.h>

#define BB 8
#define SS 1024
#define HH 1024
#define VV 512
#define LL 6

// ---------------- scratch (device globals; no allocation allowed) -------------
__device__ float g_x[BB * SS * HH];
__device__ float g_qkv[BB * SS * 3 * HH];       // fused qkv output [8192][3072]
__device__ float g_at[BB * SS * SS];            // attn^T
__device__ float g_vt[BB * SS * HH];            // v^T
__device__ float g_c[BB * SS * HH];
__device__ float g_wqkvt[LL * 3 * HH * HH];     // packed transposed Wq|Wk|Wv
__device__ float g_bqkv[LL * 3 * HH];           // packed bq|bk|bv
__device__ float g_wmt[LL * HH * HH];
__device__ float g_wot[HH * VV];

// ---------------- helpers ------------------------------------------------------
__device__ __forceinline__ uint32_t to_tf32(float x) {
    uint32_t r;
    asm("cvt.rna.tf32.f32 %0, %1;" : "=r"(r) : "f"(x));
    return r;
}
__device__ __forceinline__ void mma_tf32(float* c, const uint32_t* a,
                                         uint32_t b0, uint32_t b1) {
    asm volatile(
        "mma.sync.aligned.m16n8k8.row.col.f32.tf32.tf32.f32 "
        "{%0,%1,%2,%3}, {%4,%5,%6,%7}, {%8,%9}, {%0,%1,%2,%3};"
        : "+f"(c[0]), "+f"(c[1]), "+f"(c[2]), "+f"(c[3])
        : "r"(a[0]), "r"(a[1]), "r"(a[2]), "r"(a[3]), "r"(b0), "r"(b1));
}

// ---------------- small kernels -------------------------------------------------
__global__ void embed_kernel(float* __restrict__ x, const float* __restrict__ emb,
                             const int* __restrict__ ids) {
    int t = blockIdx.x * blockDim.x + threadIdx.x;
    int row = t >> 8;
    int c4  = t & 255;
    const float4* src = (const float4*)(emb + (size_t)ids[row] * HH);
    ((float4*)(x + (size_t)row * HH))[c4] = src[c4];
}

__global__ void bias_pack_kernel(const float* __restrict__ bq,
                                 const float* __restrict__ bk,
                                 const float* __restrict__ bv,
                                 float* __restrict__ out) {
    int t = blockIdx.x * blockDim.x + threadIdx.x;   // over LL*3*HH
    int l = t / (3 * HH);
    int j = t % (3 * HH);
    float v;
    if (j < HH)           v = bq[l * HH + j];
    else if (j < 2 * HH)  v = bk[l * HH + j - HH];
    else                  v = bv[l * HH + j - 2 * HH];
    out[t] = v;
}

// out[z][c][r] = in[z][r][c]; in row stride in_ld, batch strides in_bs/out_bs
__global__ void transpose_kernel(const float* __restrict__ in, float* __restrict__ out,
                                 int R, int C, int in_ld, size_t in_bs, size_t out_bs) {
    __shared__ float t[32][33];
    const float* ip = in + (size_t)blockIdx.z * in_bs;
    float* op = out + (size_t)blockIdx.z * out_bs;
    int c0 = blockIdx.x * 32, r0 = blockIdx.y * 32;
    int x = threadIdx.x, y = threadIdx.y;
#pragma unroll
    for (int j = 0; j < 32; j += 8)
        t[y + j][x] = ip[(size_t)(r0 + y + j) * in_ld + c0 + x];
    __syncthreads();
#pragma unroll
    for (int j = 0; j < 32; j += 8)
        op[(size_t)(c0 + y + j) * R + r0 + x] = t[x][y + j];
}

// ---------------- single-product TF32 tensor-core GEMM ---------------------------
// C[M,N] = alpha * A @ B^T (+bias[n]); A:[M,K] lda, B:[N,K] ldb (both K-contig).
// CTA tile 128(M) x BN(N), K-chunk 32, 8 warps, tf32 mma m16n8k8.
//   BN=256: warp subtile 64x64 ; BN=128: warp subtile 32x64
// EPI=1: C = res1 + res2 + relu(acc + bias)
// mode: 0 none, 1 causal K clamp (Kend=m0+128) + heavy-first y-flip,
//       2 skip tile if m0 > n0+BN-1
static constexpr int RP = 36;                         // padded row, floats
template <int BN> static constexpr int smem_floats() {
    return (128 * RP + BN * RP) * 2;
}

template <int EPI, int BN>
__global__ __launch_bounds__(256, 1) void mma_gemm(
    const float* __restrict__ A, const float* __restrict__ B, float* __restrict__ C,
    int K, int lda, int ldb, int ldc, float alpha,
    const float* __restrict__ bias,
    const float* __restrict__ res1, const float* __restrict__ res2,
    size_t bsA, size_t bsB, size_t bsC, int mode)
{
    constexpr int SMEM_A_FLOATS = 128 * RP;
    constexpr int SMEM_B_FLOATS = BN * RP;
    constexpr int BUF_FLOATS    = SMEM_A_FLOATS + SMEM_B_FLOATS;
    constexpr int MF = (BN == 256) ? 4 : 2;           // m-fragments per warp
    constexpr int LB = BN / 32;                       // B-load iterations

    extern __shared__ float sm[];
    const int my = (mode == 1) ? (gridDim.y - 1 - blockIdx.y) : blockIdx.y;
    const int m0 = my * 128;
    const int n0 = blockIdx.x * BN;
    if (mode == 2 && m0 > n0 + BN - 1) return;
    const int bz = blockIdx.z;
    A += (size_t)bz * bsA;
    B += (size_t)bz * bsB;
    C += (size_t)bz * bsC;
    const int Kend = (mode == 1) ? ((m0 + 128 < K) ? m0 + 128 : K) : K;
    const int nch = Kend >> 5;

    const int tid  = threadIdx.x;
    const int lane = tid & 31;
    const int wid  = tid >> 5;
    const int wm   = (BN == 256) ? (wid & 1) : (wid & 3);   // m block
    const int wn   = (BN == 256) ? (wid >> 1) : (wid >> 2); // n block (x64)
    const int mrow = wm * (MF * 16);
    const int g    = lane >> 2;    // 0..7
    const int tig  = lane & 3;     // 0..3

    float acc[MF][8][4];
#pragma unroll
    for (int i = 0; i < MF; i++)
#pragma unroll
        for (int j = 0; j < 8; j++)
#pragma unroll
            for (int x = 0; x < 4; x++) acc[i][j][x] = 0.f;

    float4 rA[4], rB[LB];

    auto loadA = [&](int kc) {
        const int k0 = kc * 32;
#pragma unroll
        for (int i = 0; i < 4; i++) {
            int idx = tid + 256 * i;
            int r = idx >> 3, c4 = idx & 7;
            rA[i] = *(const float4*)(A + (size_t)(m0 + r) * lda + k0 + c4 * 4);
        }
    };
    auto loadB = [&](int kc) {
        const int k0 = kc * 32;
#pragma unroll
        for (int i = 0; i < LB; i++) {
            int idx = tid + 256 * i;
            int r = idx >> 3, c4 = idx & 7;
            rB[i] = *(const float4*)(B + (size_t)(n0 + r) * ldb + k0 + c4 * 4);
        }
    };
    auto storeAB = [&](int bufsel) {
        float* bA = sm + bufsel * BUF_FLOATS;
        float* bB = bA + SMEM_A_FLOATS;
#pragma unroll
        for (int i = 0; i < 4; i++) {
            int idx = tid + 256 * i;
            int r = idx >> 3, c4 = idx & 7;
            uint4 t;
            t.x = to_tf32(rA[i].x); t.y = to_tf32(rA[i].y);
            t.z = to_tf32(rA[i].z); t.w = to_tf32(rA[i].w);
            *(uint4*)(bA + r * RP + c4 * 4) = t;
        }
#pragma unroll
        for (int i = 0; i < LB; i++) {
            int idx = tid + 256 * i;
            int r = idx >> 3, c4 = idx & 7;
            uint4 t;
            t.x = to_tf32(rB[i].x); t.y = to_tf32(rB[i].y);
            t.z = to_tf32(rB[i].z); t.w = to_tf32(rB[i].w);
            *(uint4*)(bB + r * RP + c4 * 4) = t;
        }
    };

    loadA(0); loadB(0); storeAB(0);
    __syncthreads();

    for (int c = 0; c < nch; c++) {
        const float* sA = sm + (c & 1) * BUF_FLOATS;
        const float* sB = sA + SMEM_A_FLOATS;
        const bool pf = (c + 1 < nch);
        if (pf) { loadA(c + 1); loadB(c + 1); }

#pragma unroll
        for (int ks = 0; ks < 4; ks++) {
            const int kb = ks * 8;
            uint32_t af[MF][4];
#pragma unroll
            for (int mf = 0; mf < MF; mf++) {
                const float* ap = sA + (mrow + mf * 16 + g) * RP + kb + tig;
                af[mf][0] = __float_as_uint(ap[0]);
                af[mf][1] = __float_as_uint(ap[8 * RP]);
                af[mf][2] = __float_as_uint(ap[4]);
                af[mf][3] = __float_as_uint(ap[8 * RP + 4]);
            }
#pragma unroll
            for (int nf = 0; nf < 8; nf++) {
                const float* bp = sB + (wn * 64 + nf * 8 + g) * RP + kb + tig;
                uint32_t b0 = __float_as_uint(bp[0]);
                uint32_t b1 = __float_as_uint(bp[4]);
#pragma unroll
                for (int mf = 0; mf < MF; mf++)
                    mma_tf32(acc[mf][nf], af[mf], b0, b1);
            }
        }

        if (pf) storeAB((c + 1) & 1);
        __syncthreads();
    }

    // ---- epilogue ----
#pragma unroll
    for (int mf = 0; mf < MF; mf++) {
        const int r0 = m0 + mrow + mf * 16 + g;
#pragma unroll
        for (int nf = 0; nf < 8; nf++) {
            const int col = n0 + wn * 64 + nf * 8 + tig * 2;
            float2 v0, v1;
            v0.x = acc[mf][nf][0] * alpha; v0.y = acc[mf][nf][1] * alpha;
            v1.x = acc[mf][nf][2] * alpha; v1.y = acc[mf][nf][3] * alpha;
            if (bias) {
                float2 bb = *(const float2*)(bias + col);
                v0.x += bb.x; v0.y += bb.y; v1.x += bb.x; v1.y += bb.y;
            }
            size_t i0 = (size_t)r0 * ldc + col;
            size_t i1 = i0 + (size_t)8 * ldc;
            if (EPI == 1) {
                float2 p0 = *(const float2*)(res1 + i0), q0 = *(const float2*)(res2 + i0);
                float2 p1 = *(const float2*)(res1 + i1), q1 = *(const float2*)(res2 + i1);
                v0.x = p0.x + q0.x + fmaxf(v0.x, 0.f);
                v0.y = p0.y + q0.y + fmaxf(v0.y, 0.f);
                v1.x = p1.x + q1.x + fmaxf(v1.x, 0.f);
                v1.y = p1.y + q1.y + fmaxf(v1.y, 0.f);
            }
            *(float2*)(C + i0) = v0;
            *(float2*)(C + i1) = v1;
        }
    }
}

// ---------------- causal softmax over key axis + transposed copy ----------------
// attn[b,k,q] in d_out (softmax over k, zeros for k>q); also writes attnT[b,q,k].
// grid: BB*32 blocks (32 q per block), 256 threads = 8 k-slices x 32 q.
__global__ void softmax_kernel(float* __restrict__ attn, float* __restrict__ attnT) {
    __shared__ float rm[8][32], rs[8][32], fM[32], fI[32];
    __shared__ float tile[32][33];
    const int b = blockIdx.x >> 5, qg = blockIdx.x & 31;
    float* base  = attn  + (size_t)b * SS * SS + qg * 32;
    float* baseT = attnT + (size_t)b * SS * SS + (size_t)(qg * 32) * SS;
    const int t  = threadIdx.x;
    const int qi = t & 31;
    const int ks = t >> 5;
    const int q  = qg * 32 + qi;

    float m = -3.4e38f, s = 0.f;
    for (int k = ks; k <= q; k += 8) {
        float x = base[(size_t)k * SS + qi];
        if (x > m) { s = s * __expf(m - x) + 1.f; m = x; }
        else         s += __expf(x - m);
    }
    rm[ks][qi] = m; rs[ks][qi] = s;
    __syncthreads();
    if (t < 32) {
        float M = rm[0][qi];
#pragma unroll
        for (int i = 1; i < 8; i++) M = fmaxf(M, rm[i][qi]);
        float S = 0.f;
#pragma unroll
        for (int i = 0; i < 8; i++) S += rs[i][qi] * __expf(rm[i][qi] - M);
        fM[qi] = M; fI[qi] = 1.f / S;
    }
    __syncthreads();
    const float M = fM[qi], inv = fI[qi];

    for (int kb = 0; kb < 32; kb++) {
#pragma unroll
        for (int j = 0; j < 4; j++) {
            int k = kb * 32 + ks + 8 * j;
            float v = 0.f;
            if (k <= q) v = __expf(base[(size_t)k * SS + qi] - M) * inv;
            base[(size_t)k * SS + qi] = v;
            tile[ks + 8 * j][qi] = v;
        }
        __syncthreads();
        {
            int r = t >> 3, cq = (t & 7) * 4;
            float4 o;
            o.x = tile[cq + 0][r];
            o.y = tile[cq + 1][r];
            o.z = tile[cq + 2][r];
            o.w = tile[cq + 3][r];
            *(float4*)(baseT + (size_t)r * SS + kb * 32 + cq) = o;
        }
        __syncthreads();
    }
}

// ---------------- launch --------------------------------------------------------
extern "C" void kernel_launch(void* const* d_in, const int* in_sizes, int n_in,
                              void* d_out, int out_size) {
    (void)in_sizes; (void)n_in; (void)out_size;

    const int*   inputs    = (const int*)  d_in[0];
    const float* embedding = (const float*)d_in[1];
    const float* Wq = (const float*)d_in[2];
    const float* bq = (const float*)d_in[3];
    const float* Wk = (const float*)d_in[4];
    const float* bk = (const float*)d_in[5];
    const float* Wv = (const float*)d_in[6];
    const float* bv = (const float*)d_in[7];
    const float* Wm = (const float*)d_in[8];
    const float* bm = (const float*)d_in[9];
    const float* Wout = (const float*)d_in[10];
    const float* bout = (const float*)d_in[11];

    float* out   = (float*)d_out;                  // [B,S,V]
    float* attns = out + (size_t)BB * SS * VV;     // [L,B,S,S]

    float *xp, *qkvp, *atp, *vtp, *cp, *wqkvt, *bqkv, *wmt, *wot;
    cudaGetSymbolAddress((void**)&xp, g_x);
    cudaGetSymbolAddress((void**)&qkvp, g_qkv);
    cudaGetSymbolAddress((void**)&atp, g_at);
    cudaGetSymbolAddress((void**)&vtp, g_vt);
    cudaGetSymbolAddress((void**)&cp, g_c);
    cudaGetSymbolAddress((void**)&wqkvt, g_wqkvt);
    cudaGetSymbolAddress((void**)&bqkv, g_bqkv);
    cudaGetSymbolAddress((void**)&wmt, g_wmt);
    cudaGetSymbolAddress((void**)&wot, g_wot);

    const int SMEM_256 = smem_floats<256>() * 4;   // 110592
    const int SMEM_128 = smem_floats<128>() * 4;   // 73728
    cudaFuncSetAttribute(mma_gemm<0, 256>, cudaFuncAttributeMaxDynamicSharedMemorySize, SMEM_256);
    cudaFuncSetAttribute(mma_gemm<1, 256>, cudaFuncAttributeMaxDynamicSharedMemorySize, SMEM_256);
    cudaFuncSetAttribute(mma_gemm<0, 128>, cudaFuncAttributeMaxDynamicSharedMemorySize, SMEM_128);

    // side stream + events for graph-parallel branches (created once; reused)
    static cudaStream_t s1 = nullptr;
    static cudaEvent_t ev_fork = nullptr, ev_wt = nullptr, ev_qkv = nullptr, ev_vt = nullptr;
    if (!s1) {
        cudaStreamCreateWithFlags(&s1, cudaStreamNonBlocking);
        cudaEventCreateWithFlags(&ev_fork, cudaEventDisableTiming);
        cudaEventCreateWithFlags(&ev_wt,   cudaEventDisableTiming);
        cudaEventCreateWithFlags(&ev_qkv,  cudaEventDisableTiming);
        cudaEventCreateWithFlags(&ev_vt,   cudaEventDisableTiming);
    }

    const float scale = 0.03125f;  // 1/sqrt(1024)

    // fork: weight transposes + bias pack on s1, embed on main
    cudaEventRecord(ev_fork, 0);
    cudaStreamWaitEvent(s1, ev_fork, 0);
    {
        dim3 blk(32, 8);
        dim3 gHH(HH / 32, HH / 32, LL);
        // packed qkv weights: rows [0,H)=Wq^T, [H,2H)=Wk^T, [2H,3H)=Wv^T per layer
        transpose_kernel<<<gHH, blk, 0, s1>>>(Wq, wqkvt, HH, HH, HH,
                                              (size_t)HH * HH, (size_t)3 * HH * HH);
        transpose_kernel<<<gHH, blk, 0, s1>>>(Wk, wqkvt + (size_t)HH * HH, HH, HH, HH,
                                              (size_t)HH * HH, (size_t)3 * HH * HH);
        transpose_kernel<<<gHH, blk, 0, s1>>>(Wv, wqkvt + (size_t)2 * HH * HH, HH, HH, HH,
                                              (size_t)HH * HH, (size_t)3 * HH * HH);
        transpose_kernel<<<gHH, blk, 0, s1>>>(Wm, wmt, HH, HH, HH,
                                              (size_t)HH * HH, (size_t)HH * HH);
        dim3 gO(VV / 32, HH / 32, 1);
        transpose_kernel<<<gO, blk, 0, s1>>>(Wout, wot, HH, VV, VV, 0, 0);
        bias_pack_kernel<<<(LL * 3 * HH) / 256, 256, 0, s1>>>(bq, bk, bv, bqkv);
        cudaEventRecord(ev_wt, s1);
    }
    embed_kernel<<<BB * SS * HH / 4 / 256, 256>>>(xp, embedding, inputs);
    cudaStreamWaitEvent(0, ev_wt, 0);

    for (int l = 0; l < LL; l++) {
        const float* wqkvt_l = wqkvt + (size_t)l * 3 * HH * HH;
        const float* bqkv_l  = bqkv + (size_t)l * 3 * HH;
        const float* wmt_l = wmt + (size_t)l * HH * HH;
        const float* bm_l = bm + (size_t)l * HH;
        float* attn_l = attns + (size_t)l * BB * SS * SS;

        float* qp = qkvp;                 // cols [0,1024)    row stride 3072
        float* kp = qkvp + HH;            // cols [1024,2048)
        float* vp = qkvp + 2 * HH;        // cols [2048,3072)

        // fused qkv = x @ [Wq|Wk|Wv]^T + [bq|bk|bv]
        dim3 gQKV(3 * HH / 256, BB * SS / 128, 1);   // (12, 64)
        mma_gemm<0, 256><<<gQKV, 256, SMEM_256>>>(xp, wqkvt_l, qkvp, HH, HH, HH,
                                                  3 * HH, 1.f, bqkv_l,
                                                  nullptr, nullptr, 0, 0, 0, 0);
        cudaEventRecord(ev_qkv, 0);
        cudaStreamWaitEvent(s1, ev_qkv, 0);
        {
            // v^T: in rows=SS (stride 3*HH), out [HH][SS] dense, per batch b
            dim3 blk(32, 8);
            dim3 gV(HH / 32, SS / 32, BB);
            transpose_kernel<<<gV, blk, 0, s1>>>(vp, vtp, SS, HH, 3 * HH,
                                                 (size_t)SS * 3 * HH, (size_t)SS * HH);
            cudaEventRecord(ev_vt, s1);
        }

        // logits[b,k,q] = scale * K[b] @ Q[b]^T ; BN=128 tiles, skip masked
        dim3 gAtt(SS / 128, SS / 128, BB);           // (8, 8, 8)
        mma_gemm<0, 128><<<gAtt, 256, SMEM_128>>>(kp, qp, attn_l, HH, 3 * HH, 3 * HH,
                                                  SS, scale, nullptr, nullptr, nullptr,
                                                  (size_t)SS * 3 * HH, (size_t)SS * 3 * HH,
                                                  (size_t)SS * SS, 2);

        // softmax over key axis; attnT into g_at
        softmax_kernel<<<BB * 32, 256>>>(attn_l, atp);

        // ctx[b,q,h] = attnT[b] @ vt[b]^T ; causal K clamp, heavy-first order
        cudaStreamWaitEvent(0, ev_vt, 0);
        dim3 gCtx(HH / 256, SS / 128, BB);           // (4, 8, 8)
        mma_gemm<0, 256><<<gCtx, 256, SMEM_256>>>(atp, vtp, cp, SS, SS, SS, HH, 1.f,
                                                  nullptr, nullptr, nullptr,
                                                  (size_t)SS * SS, (size_t)SS * HH,
                                                  (size_t)SS * HH, 1);

        // x = x + ctx + relu(ctx@Wm + bm)
        dim3 gProj(HH / 256, BB * SS / 128, 1);      // (4, 64)
        mma_gemm<1, 256><<<gProj, 256, SMEM_256>>>(cp, wmt_l, xp, HH, HH, HH, HH, 1.f,
                                                   bm_l, xp, cp, 0, 0, 0, 0);
    }

    // out = x @ Wout + bout
    dim3 gOut(VV / 256, BB * SS / 128, 1);           // (2, 64)
    mma_gemm<0, 256><<<gOut, 256, SMEM_256>>>(xp, wot, out, HH, HH, HH, VV, 1.f,
                                              bout, nullptr, nullptr, 0, 0, 0, 0);
}